// round 1
// baseline (speedup 1.0000x reference)
#include <cuda_runtime.h>
#include <math.h>

// Problem constants
#define Bn  4
#define Sn  2048
#define Dn  1024
#define Hn  16
#define HDn 64
#define MTOK (Bn * Sn)   // 8192 tokens

// Scratch (allocation-free rule: __device__ globals)
__device__ float g_Q[MTOK * Dn];
__device__ float g_K[MTOK * Dn];
__device__ float g_V[MTOK * Dn];
__device__ float g_X[MTOK * Dn];

// ---------------------------------------------------------------------------
// GEMM: Y[M,N] = X[M,K] * W[N,K]^T + bias[N]   (both operands K-major)
// 64x64 tile, BK=16, 256 threads, 4x4 microtile per thread.
// Smem stored K-transposed ([BK][BM]) with 68-float row stride so the inner
// loop does aligned float4 loads (stride 68 words => 16B-aligned rows).
// ---------------------------------------------------------------------------
__global__ void __launch_bounds__(256, 4)
gemm_bias_kernel(const float* __restrict__ X, const float* __restrict__ W,
                 const float* __restrict__ bias, float* __restrict__ Y,
                 int M, int N, int K)
{
    __shared__ float As[16][68];   // [k][m]
    __shared__ float Bs[16][68];   // [k][n]

    const int tid = threadIdx.x;
    const int bm = blockIdx.y * 64;
    const int bn = blockIdx.x * 64;
    const int tx = tid & 15;       // n group
    const int ty = tid >> 4;       // m group

    const int lr = tid >> 2;          // 0..63: row within tile (load phase)
    const int lk = (tid & 3) * 4;     // 0,4,8,12: k offset (load phase)

    const float* Xp = X + (size_t)(bm + lr) * K + lk;
    const float* Wp = W + (size_t)(bn + lr) * K + lk;

    float acc[4][4];
#pragma unroll
    for (int i = 0; i < 4; i++)
#pragma unroll
        for (int j = 0; j < 4; j++) acc[i][j] = 0.f;

    for (int k0 = 0; k0 < K; k0 += 16) {
        float4 a = *(const float4*)(Xp + k0);
        float4 b = *(const float4*)(Wp + k0);
        As[lk + 0][lr] = a.x; As[lk + 1][lr] = a.y;
        As[lk + 2][lr] = a.z; As[lk + 3][lr] = a.w;
        Bs[lk + 0][lr] = b.x; Bs[lk + 1][lr] = b.y;
        Bs[lk + 2][lr] = b.z; Bs[lk + 3][lr] = b.w;
        __syncthreads();

#pragma unroll
        for (int kk = 0; kk < 16; kk++) {
            float4 av = *(const float4*)&As[kk][ty * 4];
            float4 bv = *(const float4*)&Bs[kk][tx * 4];
            float ar[4] = {av.x, av.y, av.z, av.w};
            float br[4] = {bv.x, bv.y, bv.z, bv.w};
#pragma unroll
            for (int i = 0; i < 4; i++)
#pragma unroll
                for (int j = 0; j < 4; j++)
                    acc[i][j] = fmaf(ar[i], br[j], acc[i][j]);
        }
        __syncthreads();
    }

#pragma unroll
    for (int i = 0; i < 4; i++) {
        float* yp = Y + (size_t)(bm + ty * 4 + i) * N + bn + tx * 4;
#pragma unroll
        for (int j = 0; j < 4; j++)
            yp[j] = acc[i][j] + bias[bn + tx * 4 + j];
    }
}

// ---------------------------------------------------------------------------
// Flash attention fp32. One CTA = one (b,h) x 64-query tile.
// 256 threads: thread t handles q-row r = t/4, dims [ql*16, ql*16+16) where
// ql = t%4. Quad shfl-reduce completes each QK^T dot. Online softmax in
// 16-key chunks keeps the score fragment at 16 registers.
// Q is pre-scaled by 1/sqrt(HD).
// ---------------------------------------------------------------------------
__global__ void __launch_bounds__(256, 3)
flash_attn_kernel(const float* __restrict__ Q, const float* __restrict__ K,
                  const float* __restrict__ V, float* __restrict__ O)
{
    __shared__ float Ks[64][68];
    __shared__ float Vs[64][68];

    const int bh = blockIdx.y;
    const int b  = bh / Hn;
    const int h  = bh % Hn;
    const int q0 = blockIdx.x * 64;

    const int tid = threadIdx.x;
    const int r   = tid >> 2;   // q row in tile
    const int ql  = tid & 3;    // quad lane -> dim slice

    const float scale = 0.125f;  // 1/sqrt(64)

    // Load & pre-scale my Q fragment (16 dims)
    float qf[16];
    {
        const float* qp = Q + ((size_t)(b * Sn + q0 + r) * Dn) + h * HDn + ql * 16;
#pragma unroll
        for (int u = 0; u < 4; u++) {
            float4 t = *(const float4*)(qp + u * 4);
            qf[u * 4 + 0] = t.x * scale;
            qf[u * 4 + 1] = t.y * scale;
            qf[u * 4 + 2] = t.z * scale;
            qf[u * 4 + 3] = t.w * scale;
        }
    }

    float of[16];
#pragma unroll
    for (int d = 0; d < 16; d++) of[d] = 0.f;
    float mi = -INFINITY;
    float li = 0.f;

    for (int k0 = 0; k0 < Sn; k0 += 64) {
        // Cooperative K/V tile load: thread loads row tid/4, 16 floats (4x float4)
        {
            const size_t rowoff = ((size_t)(b * Sn + k0 + r) * Dn) + h * HDn;
            const float* kp = K + rowoff;
            const float* vp = V + rowoff;
#pragma unroll
            for (int u = 0; u < 4; u++) {
                int d = ql * 4 + u * 16;
                *(float4*)&Ks[r][d] = *(const float4*)(kp + d);
                *(float4*)&Vs[r][d] = *(const float4*)(vp + d);
            }
        }
        __syncthreads();

#pragma unroll 1
        for (int c = 0; c < 4; c++) {   // 16-key chunks
            float s[16];
#pragma unroll
            for (int j = 0; j < 16; j++) {
                const int jj = c * 16 + j;
                float a = 0.f;
#pragma unroll
                for (int d = 0; d < 16; d += 4) {
                    float4 kv = *(const float4*)&Ks[jj][ql * 16 + d];
                    a = fmaf(qf[d + 0], kv.x, a);
                    a = fmaf(qf[d + 1], kv.y, a);
                    a = fmaf(qf[d + 2], kv.z, a);
                    a = fmaf(qf[d + 3], kv.w, a);
                }
                a += __shfl_xor_sync(0xffffffffu, a, 1);
                a += __shfl_xor_sync(0xffffffffu, a, 2);
                s[j] = a;
            }

            float mloc = s[0];
#pragma unroll
            for (int j = 1; j < 16; j++) mloc = fmaxf(mloc, s[j]);
            const float mnew = fmaxf(mi, mloc);
            const float corr = __expf(mi - mnew);

            float psum = 0.f;
#pragma unroll
            for (int j = 0; j < 16; j++) {
                s[j] = __expf(s[j] - mnew);
                psum += s[j];
            }
            li = li * corr + psum;
            mi = mnew;

#pragma unroll
            for (int d = 0; d < 16; d++) of[d] *= corr;

#pragma unroll
            for (int j = 0; j < 16; j++) {
                const int jj = c * 16 + j;
                const float p = s[j];
#pragma unroll
                for (int d = 0; d < 16; d += 4) {
                    float4 vv = *(const float4*)&Vs[jj][ql * 16 + d];
                    of[d + 0] = fmaf(p, vv.x, of[d + 0]);
                    of[d + 1] = fmaf(p, vv.y, of[d + 1]);
                    of[d + 2] = fmaf(p, vv.z, of[d + 2]);
                    of[d + 3] = fmaf(p, vv.w, of[d + 3]);
                }
            }
        }
        __syncthreads();
    }

    const float inv = 1.f / li;
    float* op = O + ((size_t)(b * Sn + q0 + r) * Dn) + h * HDn + ql * 16;
#pragma unroll
    for (int u = 0; u < 4; u++) {
        float4 t;
        t.x = of[u * 4 + 0] * inv;
        t.y = of[u * 4 + 1] * inv;
        t.z = of[u * 4 + 2] * inv;
        t.w = of[u * 4 + 3] * inv;
        *(float4*)(op + u * 4) = t;
    }
}

// ---------------------------------------------------------------------------
// kernel_launch: 3 projections -> attention -> output projection
// ---------------------------------------------------------------------------
extern "C" void kernel_launch(void* const* d_in, const int* in_sizes, int n_in,
                              void* d_out, int out_size)
{
    (void)in_sizes; (void)n_in; (void)out_size;

    const float* q    = (const float*)d_in[0];
    const float* k    = (const float*)d_in[1];
    const float* v    = (const float*)d_in[2];
    const float* w_q  = (const float*)d_in[3];
    const float* b_q  = (const float*)d_in[4];
    const float* w_k  = (const float*)d_in[5];
    const float* b_k  = (const float*)d_in[6];
    const float* w_v  = (const float*)d_in[7];
    const float* b_v  = (const float*)d_in[8];
    const float* w_fc = (const float*)d_in[9];
    const float* b_fc = (const float*)d_in[10];
    float* out = (float*)d_out;

    float *gQ, *gK, *gV, *gX;
    cudaGetSymbolAddress((void**)&gQ, g_Q);
    cudaGetSymbolAddress((void**)&gK, g_K);
    cudaGetSymbolAddress((void**)&gV, g_V);
    cudaGetSymbolAddress((void**)&gX, g_X);

    dim3 gemm_grid(Dn / 64, MTOK / 64);   // (16, 128)
    dim3 gemm_blk(256);

    gemm_bias_kernel<<<gemm_grid, gemm_blk>>>(q, w_q, b_q, gQ, MTOK, Dn, Dn);
    gemm_bias_kernel<<<gemm_grid, gemm_blk>>>(k, w_k, b_k, gK, MTOK, Dn, Dn);
    gemm_bias_kernel<<<gemm_grid, gemm_blk>>>(v, w_v, b_v, gV, MTOK, Dn, Dn);

    dim3 attn_grid(Sn / 64, Bn * Hn);     // (32, 64)
    flash_attn_kernel<<<attn_grid, dim3(256)>>>(gQ, gK, gV, gX);

    gemm_bias_kernel<<<gemm_grid, gemm_blk>>>(gX, w_fc, b_fc, out, MTOK, Dn, Dn);
}

// round 3
// speedup vs baseline: 2.4157x; 2.4157x over previous
#include <cuda_runtime.h>
#include <cuda_bf16.h>
#include <cstdint>
#include <math.h>

#define Bn  4
#define Sn  2048
#define Dn  1024
#define Hn  16
#define HDn 64
#define MTOK (Bn * Sn)   // 8192

// Scratch (allocation-free rule)
__device__ float g_Q[MTOK * Dn];
__device__ float g_K[MTOK * Dn];
__device__ float g_V[MTOK * Dn];
__device__ float g_X[MTOK * Dn];

// ---------------------------------------------------------------------------
// bf16 hi/lo split helpers
// ---------------------------------------------------------------------------
__device__ __forceinline__ uint32_t pack_bf2(__nv_bfloat16 a, __nv_bfloat16 b) {
    __nv_bfloat162 t(a, b);
    return *reinterpret_cast<uint32_t*>(&t);
}

__device__ __forceinline__ void split2(float x, float y, uint32_t& hi, uint32_t& lo) {
    __nv_bfloat16 hx = __float2bfloat16_rn(x);
    __nv_bfloat16 hy = __float2bfloat16_rn(y);
    __nv_bfloat16 lx = __float2bfloat16_rn(x - __bfloat162float(hx));
    __nv_bfloat16 ly = __float2bfloat16_rn(y - __bfloat162float(hy));
    hi = pack_bf2(hx, hy);
    lo = pack_bf2(lx, ly);
}

// mma.sync m16n8k16 row.col f32.bf16.bf16.f32
__device__ __forceinline__ void mma16816(float* d, const uint32_t* a, const uint32_t* b) {
    asm volatile(
        "mma.sync.aligned.m16n8k16.row.col.f32.bf16.bf16.f32 "
        "{%0,%1,%2,%3}, {%4,%5,%6,%7}, {%8,%9}, {%0,%1,%2,%3};"
        : "+f"(d[0]), "+f"(d[1]), "+f"(d[2]), "+f"(d[3])
        : "r"(a[0]), "r"(a[1]), "r"(a[2]), "r"(a[3]), "r"(b[0]), "r"(b[1]));
}

// ---------------------------------------------------------------------------
// GEMM: Y[M,N] = X[M,K] * W[N,K]^T + bias, via mma.sync bf16 hi/lo split.
// CTA 128x128, BK=32, 256 threads (8 warps, 2x4), warp tile 64x32.
// smem padded stride 40 bf16 (80B): fragment loads bank-conflict-free.
// ---------------------------------------------------------------------------
#define BM 128
#define BN 128
#define BK 32
#define SST 40

__global__ void __launch_bounds__(256, 2)
gemm_mma_kernel(const float* __restrict__ X, const float* __restrict__ W,
                const float* __restrict__ bias, float* __restrict__ Y)
{
    __shared__ __align__(16) __nv_bfloat16 sAhi[BM][SST];
    __shared__ __align__(16) __nv_bfloat16 sAlo[BM][SST];
    __shared__ __align__(16) __nv_bfloat16 sBhi[BN][SST];
    __shared__ __align__(16) __nv_bfloat16 sBlo[BN][SST];

    const int tid  = threadIdx.x;
    const int wid  = tid >> 5;
    const int lane = tid & 31;
    const int bm = blockIdx.y * BM;
    const int bn = blockIdx.x * BN;
    const int wm = (wid & 1) * 64;    // warp m offset in tile
    const int wn = (wid >> 1) * 32;   // warp n offset in tile

    float acc[4][4][4];
#pragma unroll
    for (int mt = 0; mt < 4; mt++)
#pragma unroll
        for (int nt = 0; nt < 4; nt++)
#pragma unroll
            for (int e = 0; e < 4; e++) acc[mt][nt][e] = 0.f;

    const int fr = lane >> 2;          // fragment row group 0..7
    const int fc = (lane & 3) * 2;     // fragment col pair

    for (int k0 = 0; k0 < Dn; k0 += BK) {
        // Load & split: per operand 128 rows x 32 floats; 8 threads/row
#pragma unroll
        for (int i = 0; i < 4; i++) {
            int idx = tid + i * 256;
            int row = idx >> 3;
            int c4  = (idx & 7) << 2;
            float4 xa = *(const float4*)(X + (size_t)(bm + row) * Dn + k0 + c4);
            float4 wb = *(const float4*)(W + (size_t)(bn + row) * Dn + k0 + c4);
            uint32_t h01, l01, h23, l23;
            split2(xa.x, xa.y, h01, l01);
            split2(xa.z, xa.w, h23, l23);
            *(uint32_t*)&sAhi[row][c4]     = h01;
            *(uint32_t*)&sAhi[row][c4 + 2] = h23;
            *(uint32_t*)&sAlo[row][c4]     = l01;
            *(uint32_t*)&sAlo[row][c4 + 2] = l23;
            split2(wb.x, wb.y, h01, l01);
            split2(wb.z, wb.w, h23, l23);
            *(uint32_t*)&sBhi[row][c4]     = h01;
            *(uint32_t*)&sBhi[row][c4 + 2] = h23;
            *(uint32_t*)&sBlo[row][c4]     = l01;
            *(uint32_t*)&sBlo[row][c4 + 2] = l23;
        }
        __syncthreads();

#pragma unroll
        for (int ks = 0; ks < 2; ks++) {
            const int kk = ks * 16;
            // A fragments (hi & lo) for 4 m-tiles
            uint32_t ahi[4][4], alo[4][4];
#pragma unroll
            for (int mt = 0; mt < 4; mt++) {
                const int m0 = wm + mt * 16;
                ahi[mt][0] = *(const uint32_t*)&sAhi[m0 + fr][kk + fc];
                ahi[mt][1] = *(const uint32_t*)&sAhi[m0 + fr + 8][kk + fc];
                ahi[mt][2] = *(const uint32_t*)&sAhi[m0 + fr][kk + fc + 8];
                ahi[mt][3] = *(const uint32_t*)&sAhi[m0 + fr + 8][kk + fc + 8];
                alo[mt][0] = *(const uint32_t*)&sAlo[m0 + fr][kk + fc];
                alo[mt][1] = *(const uint32_t*)&sAlo[m0 + fr + 8][kk + fc];
                alo[mt][2] = *(const uint32_t*)&sAlo[m0 + fr][kk + fc + 8];
                alo[mt][3] = *(const uint32_t*)&sAlo[m0 + fr + 8][kk + fc + 8];
            }
#pragma unroll
            for (int nt = 0; nt < 4; nt++) {
                const int n0 = wn + nt * 8;
                uint32_t bhi[2], blo[2];
                bhi[0] = *(const uint32_t*)&sBhi[n0 + fr][kk + fc];
                bhi[1] = *(const uint32_t*)&sBhi[n0 + fr][kk + fc + 8];
                blo[0] = *(const uint32_t*)&sBlo[n0 + fr][kk + fc];
                blo[1] = *(const uint32_t*)&sBlo[n0 + fr][kk + fc + 8];
                // NOTE: for B (col-major n8xk16): row index = n, handled by
                // fragment layout: b0 covers k=fc(+1), n=fr. fr<8 covers n8.
#pragma unroll
                for (int mt = 0; mt < 4; mt++) {
                    mma16816(acc[mt][nt], ahi[mt], bhi);
                    mma16816(acc[mt][nt], ahi[mt], blo);
                    mma16816(acc[mt][nt], alo[mt], bhi);
                }
            }
        }
        __syncthreads();
    }

    // Epilogue: float2 stores + bias
#pragma unroll
    for (int mt = 0; mt < 4; mt++) {
        const int row0 = bm + wm + mt * 16 + fr;
#pragma unroll
        for (int nt = 0; nt < 4; nt++) {
            const int col0 = bn + wn + nt * 8 + fc;
            const float bx = bias[col0], by = bias[col0 + 1];
            float2 t0 = make_float2(acc[mt][nt][0] + bx, acc[mt][nt][1] + by);
            float2 t1 = make_float2(acc[mt][nt][2] + bx, acc[mt][nt][3] + by);
            *(float2*)(Y + (size_t)row0 * Dn + col0)       = t0;
            *(float2*)(Y + (size_t)(row0 + 8) * Dn + col0) = t1;
        }
    }
}

// ---------------------------------------------------------------------------
// Register-tiled fp32 attention. CTA = (b,h) x 64-query tile. 256 thr (16x16),
// each thread owns a 4x4 microtile. S = Qt^T*Kt via smem, P routed through
// smem transposed, O accumulated in registers. Online softmax with per-thread
// replicated row stats.
// ---------------------------------------------------------------------------
#define APAD 68
#define ATTN_SMEM (3 * 64 * APAD * 4)   // 52224 bytes

__global__ void __launch_bounds__(256, 4)
attn_tile_kernel(const float* __restrict__ Q, const float* __restrict__ K,
                 const float* __restrict__ V, float* __restrict__ O)
{
    extern __shared__ float smf[];
    float* Qt = smf;                  // [d][APAD] q index
    float* KP = smf + 64 * APAD;      // Kt [d][APAD] k idx; later Pt [k][APAD] q idx
    float* Vs = smf + 2 * 64 * APAD;  // [k][APAD] d idx

    const int tid = threadIdx.x;
    const int tx = tid & 15;          // k-group (then d-group in PV)
    const int ty = tid >> 4;          // q-group
    const int bh = blockIdx.y;
    const int b = bh >> 4;
    const int h = bh & 15;
    const int q0 = blockIdx.x * 64;
    const int r = tid >> 2;
    const int ql = tid & 3;

    // Load Q tile transposed + prescaled
    {
        const float* qp = Q + ((size_t)(b * Sn + q0 + r) * Dn) + h * HDn;
#pragma unroll
        for (int u = 0; u < 4; u++) {
            int d = ql * 4 + u * 16;
            float4 t = *(const float4*)(qp + d);
            Qt[(d + 0) * APAD + r] = t.x * 0.125f;
            Qt[(d + 1) * APAD + r] = t.y * 0.125f;
            Qt[(d + 2) * APAD + r] = t.z * 0.125f;
            Qt[(d + 3) * APAD + r] = t.w * 0.125f;
        }
    }

    float o[4][4];
    float m[4], l[4];
#pragma unroll
    for (int i = 0; i < 4; i++) {
        m[i] = -1e30f; l[i] = 0.f;
#pragma unroll
        for (int j = 0; j < 4; j++) o[i][j] = 0.f;
    }
    __syncthreads();

    for (int k0 = 0; k0 < Sn; k0 += 64) {
        // Load K transposed (Kt[d][k]) and V direct (Vs[k][d])
        {
            const size_t ro = ((size_t)(b * Sn + k0 + r) * Dn) + h * HDn;
#pragma unroll
            for (int u = 0; u < 4; u++) {
                int d = ql * 4 + u * 16;
                float4 kv = *(const float4*)(K + ro + d);
                float4 vv = *(const float4*)(V + ro + d);
                KP[(d + 0) * APAD + r] = kv.x;
                KP[(d + 1) * APAD + r] = kv.y;
                KP[(d + 2) * APAD + r] = kv.z;
                KP[(d + 3) * APAD + r] = kv.w;
                *(float4*)&Vs[r * APAD + d] = vv;
            }
        }
        __syncthreads();

        // S[i][j] = sum_d Qt[d][ty*4+i] * Kt[d][tx*4+j]
        float s[4][4];
#pragma unroll
        for (int i = 0; i < 4; i++)
#pragma unroll
            for (int j = 0; j < 4; j++) s[i][j] = 0.f;

#pragma unroll 8
        for (int d = 0; d < 64; d++) {
            float4 a4 = *(const float4*)&Qt[d * APAD + ty * 4];
            float4 b4 = *(const float4*)&KP[d * APAD + tx * 4];
            float av[4] = {a4.x, a4.y, a4.z, a4.w};
            float bv[4] = {b4.x, b4.y, b4.z, b4.w};
#pragma unroll
            for (int i = 0; i < 4; i++)
#pragma unroll
                for (int j = 0; j < 4; j++)
                    s[i][j] = fmaf(av[i], bv[j], s[i][j]);
        }
        __syncthreads();   // Kt dead; KP becomes Pt

        // Online softmax (stats replicated across the 16 tx lanes)
#pragma unroll
        for (int i = 0; i < 4; i++) {
            float mx = fmaxf(fmaxf(s[i][0], s[i][1]), fmaxf(s[i][2], s[i][3]));
            mx = fmaxf(mx, __shfl_xor_sync(0xffffffffu, mx, 1));
            mx = fmaxf(mx, __shfl_xor_sync(0xffffffffu, mx, 2));
            mx = fmaxf(mx, __shfl_xor_sync(0xffffffffu, mx, 4));
            mx = fmaxf(mx, __shfl_xor_sync(0xffffffffu, mx, 8));
            float mn = fmaxf(m[i], mx);
            float corr = __expf(m[i] - mn);
            m[i] = mn;
            float sum = 0.f;
#pragma unroll
            for (int j = 0; j < 4; j++) {
                s[i][j] = __expf(s[i][j] - mn);
                sum += s[i][j];
            }
            sum += __shfl_xor_sync(0xffffffffu, sum, 1);
            sum += __shfl_xor_sync(0xffffffffu, sum, 2);
            sum += __shfl_xor_sync(0xffffffffu, sum, 4);
            sum += __shfl_xor_sync(0xffffffffu, sum, 8);
            l[i] = l[i] * corr + sum;
#pragma unroll
            for (int j = 0; j < 4; j++) o[i][j] *= corr;
        }

        // Write P transposed: Pt[k][q]
#pragma unroll
        for (int j = 0; j < 4; j++) {
            float4 t = make_float4(s[0][j], s[1][j], s[2][j], s[3][j]);
            *(float4*)&KP[(tx * 4 + j) * APAD + ty * 4] = t;
        }
        __syncthreads();

        // O[i][j] += sum_k Pt[k][ty*4+i] * Vs[k][tx*4+j]
#pragma unroll 8
        for (int k = 0; k < 64; k++) {
            float4 a4 = *(const float4*)&KP[k * APAD + ty * 4];
            float4 b4 = *(const float4*)&Vs[k * APAD + tx * 4];
            float av[4] = {a4.x, a4.y, a4.z, a4.w};
            float bv[4] = {b4.x, b4.y, b4.z, b4.w};
#pragma unroll
            for (int i = 0; i < 4; i++)
#pragma unroll
                for (int j = 0; j < 4; j++)
                    o[i][j] = fmaf(av[i], bv[j], o[i][j]);
        }
        __syncthreads();
    }

    // Output
#pragma unroll
    for (int i = 0; i < 4; i++) {
        float inv = 1.f / l[i];
        float4 t = make_float4(o[i][0] * inv, o[i][1] * inv, o[i][2] * inv, o[i][3] * inv);
        *(float4*)(O + ((size_t)(b * Sn + q0 + ty * 4 + i) * Dn) + h * HDn + tx * 4) = t;
    }
}

// ---------------------------------------------------------------------------
extern "C" void kernel_launch(void* const* d_in, const int* in_sizes, int n_in,
                              void* d_out, int out_size)
{
    (void)in_sizes; (void)n_in; (void)out_size;

    const float* q    = (const float*)d_in[0];
    const float* k    = (const float*)d_in[1];
    const float* v    = (const float*)d_in[2];
    const float* w_q  = (const float*)d_in[3];
    const float* b_q  = (const float*)d_in[4];
    const float* w_k  = (const float*)d_in[5];
    const float* b_k  = (const float*)d_in[6];
    const float* w_v  = (const float*)d_in[7];
    const float* b_v  = (const float*)d_in[8];
    const float* w_fc = (const float*)d_in[9];
    const float* b_fc = (const float*)d_in[10];
    float* out = (float*)d_out;

    cudaStreamCaptureStatus cs = cudaStreamCaptureStatusNone;
    cudaStreamIsCapturing(cudaStreamLegacy, &cs);
    if (cs == cudaStreamCaptureStatusNone) {
        cudaFuncSetAttribute(attn_tile_kernel,
                             cudaFuncAttributeMaxDynamicSharedMemorySize, ATTN_SMEM);
    }

    float *gQ, *gK, *gV, *gX;
    cudaGetSymbolAddress((void**)&gQ, g_Q);
    cudaGetSymbolAddress((void**)&gK, g_K);
    cudaGetSymbolAddress((void**)&gV, g_V);
    cudaGetSymbolAddress((void**)&gX, g_X);

    dim3 ggrid(Dn / BN, MTOK / BM);     // (8, 64)
    gemm_mma_kernel<<<ggrid, 256>>>(q, w_q, b_q, gQ);
    gemm_mma_kernel<<<ggrid, 256>>>(k, w_k, b_k, gK);
    gemm_mma_kernel<<<ggrid, 256>>>(v, w_v, b_v, gV);

    dim3 agrid(Sn / 64, Bn * Hn);       // (32, 64)
    attn_tile_kernel<<<agrid, 256, ATTN_SMEM>>>(gQ, gK, gV, gX);

    gemm_mma_kernel<<<ggrid, 256>>>(gX, w_fc, b_fc, out);
}

// round 4
// speedup vs baseline: 7.8173x; 3.2361x over previous
#include <cuda_runtime.h>
#include <cuda_bf16.h>
#include <cstdint>
#include <math.h>

#define Bn  4
#define Sn  2048
#define Dn  1024
#define Hn  16
#define HDn 64
#define MTOK (Bn * Sn)   // 8192

// Scratch (allocation-free rule)
__device__ float g_Q[MTOK * Dn];
__device__ float g_K[MTOK * Dn];
__device__ float g_V[MTOK * Dn];
__device__ float g_X[MTOK * Dn];

// ---------------------------------------------------------------------------
// Helpers
// ---------------------------------------------------------------------------
__device__ __forceinline__ uint32_t smem_u32(const void* p) {
    uint32_t a;
    asm("{ .reg .u64 t; cvta.to.shared.u64 t, %1; cvt.u32.u64 %0, t; }" : "=r"(a) : "l"(p));
    return a;
}

// Pack two floats to bf16x2 (x -> low, y -> high) + residual pair.
__device__ __forceinline__ void split2f(float x, float y, uint32_t& hi, uint32_t& lo) {
    uint32_t h;
    asm("cvt.rn.bf16x2.f32 %0, %1, %2;" : "=r"(h) : "f"(y), "f"(x));
    float hx = __uint_as_float(h << 16);
    float hy = __uint_as_float(h & 0xffff0000u);
    asm("cvt.rn.bf16x2.f32 %0, %1, %2;" : "=r"(lo) : "f"(y - hy), "f"(x - hx));
    hi = h;
}

// mma.sync m16n8k16 row.col f32.bf16.bf16.f32
__device__ __forceinline__ void mma16816(float* d, const uint32_t* a, const uint32_t* b) {
    asm volatile(
        "mma.sync.aligned.m16n8k16.row.col.f32.bf16.bf16.f32 "
        "{%0,%1,%2,%3}, {%4,%5,%6,%7}, {%8,%9}, {%0,%1,%2,%3};"
        : "+f"(d[0]), "+f"(d[1]), "+f"(d[2]), "+f"(d[3])
        : "r"(a[0]), "r"(a[1]), "r"(a[2]), "r"(a[3]), "r"(b[0]), "r"(b[1]));
}

#define LDSM_X4_T(r0, r1, r2, r3, addr) \
    asm volatile("ldmatrix.sync.aligned.m8n8.x4.trans.shared.b16 {%0,%1,%2,%3}, [%4];" \
                 : "=r"(r0), "=r"(r1), "=r"(r2), "=r"(r3) : "r"(addr))

// ---------------------------------------------------------------------------
// GEMM: Y[M,N] = X[M,K] * W[N,K]^T + bias, via mma.sync bf16 hi/lo split.
// CTA 128x128, BK=32, 256 threads (8 warps, 2x4), warp tile 64x32.
// ---------------------------------------------------------------------------
#define BM 128
#define BN 128
#define BK 32
#define SST 40

__global__ void __launch_bounds__(256, 2)
gemm_mma_kernel(const float* __restrict__ X, const float* __restrict__ W,
                const float* __restrict__ bias, float* __restrict__ Y)
{
    __shared__ __align__(16) __nv_bfloat16 sAhi[BM][SST];
    __shared__ __align__(16) __nv_bfloat16 sAlo[BM][SST];
    __shared__ __align__(16) __nv_bfloat16 sBhi[BN][SST];
    __shared__ __align__(16) __nv_bfloat16 sBlo[BN][SST];

    const int tid  = threadIdx.x;
    const int wid  = tid >> 5;
    const int lane = tid & 31;
    const int bm = blockIdx.y * BM;
    const int bn = blockIdx.x * BN;
    const int wm = (wid & 1) * 64;
    const int wn = (wid >> 1) * 32;

    float acc[4][4][4];
#pragma unroll
    for (int mt = 0; mt < 4; mt++)
#pragma unroll
        for (int nt = 0; nt < 4; nt++)
#pragma unroll
            for (int e = 0; e < 4; e++) acc[mt][nt][e] = 0.f;

    const int fr = lane >> 2;
    const int fc = (lane & 3) * 2;

    for (int k0 = 0; k0 < Dn; k0 += BK) {
#pragma unroll
        for (int i = 0; i < 4; i++) {
            int idx = tid + i * 256;
            int row = idx >> 3;
            int c4  = (idx & 7) << 2;
            float4 xa = *(const float4*)(X + (size_t)(bm + row) * Dn + k0 + c4);
            float4 wb = *(const float4*)(W + (size_t)(bn + row) * Dn + k0 + c4);
            uint32_t h01, l01, h23, l23;
            split2f(xa.x, xa.y, h01, l01);
            split2f(xa.z, xa.w, h23, l23);
            *(uint32_t*)&sAhi[row][c4]     = h01;
            *(uint32_t*)&sAhi[row][c4 + 2] = h23;
            *(uint32_t*)&sAlo[row][c4]     = l01;
            *(uint32_t*)&sAlo[row][c4 + 2] = l23;
            split2f(wb.x, wb.y, h01, l01);
            split2f(wb.z, wb.w, h23, l23);
            *(uint32_t*)&sBhi[row][c4]     = h01;
            *(uint32_t*)&sBhi[row][c4 + 2] = h23;
            *(uint32_t*)&sBlo[row][c4]     = l01;
            *(uint32_t*)&sBlo[row][c4 + 2] = l23;
        }
        __syncthreads();

#pragma unroll
        for (int ks = 0; ks < 2; ks++) {
            const int kk = ks * 16;
            uint32_t ahi[4][4], alo[4][4];
#pragma unroll
            for (int mt = 0; mt < 4; mt++) {
                const int m0 = wm + mt * 16;
                ahi[mt][0] = *(const uint32_t*)&sAhi[m0 + fr][kk + fc];
                ahi[mt][1] = *(const uint32_t*)&sAhi[m0 + fr + 8][kk + fc];
                ahi[mt][2] = *(const uint32_t*)&sAhi[m0 + fr][kk + fc + 8];
                ahi[mt][3] = *(const uint32_t*)&sAhi[m0 + fr + 8][kk + fc + 8];
                alo[mt][0] = *(const uint32_t*)&sAlo[m0 + fr][kk + fc];
                alo[mt][1] = *(const uint32_t*)&sAlo[m0 + fr + 8][kk + fc];
                alo[mt][2] = *(const uint32_t*)&sAlo[m0 + fr][kk + fc + 8];
                alo[mt][3] = *(const uint32_t*)&sAlo[m0 + fr + 8][kk + fc + 8];
            }
#pragma unroll
            for (int nt = 0; nt < 4; nt++) {
                const int n0 = wn + nt * 8;
                uint32_t bhi[2], blo[2];
                bhi[0] = *(const uint32_t*)&sBhi[n0 + fr][kk + fc];
                bhi[1] = *(const uint32_t*)&sBhi[n0 + fr][kk + fc + 8];
                blo[0] = *(const uint32_t*)&sBlo[n0 + fr][kk + fc];
                blo[1] = *(const uint32_t*)&sBlo[n0 + fr][kk + fc + 8];
#pragma unroll
                for (int mt = 0; mt < 4; mt++) {
                    mma16816(acc[mt][nt], ahi[mt], bhi);
                    mma16816(acc[mt][nt], ahi[mt], blo);
                    mma16816(acc[mt][nt], alo[mt], bhi);
                }
            }
        }
        __syncthreads();
    }

#pragma unroll
    for (int mt = 0; mt < 4; mt++) {
        const int row0 = bm + wm + mt * 16 + fr;
#pragma unroll
        for (int nt = 0; nt < 4; nt++) {
            const int col0 = bn + wn + nt * 8 + fc;
            const float bx = bias[col0], by = bias[col0 + 1];
            float2 t0 = make_float2(acc[mt][nt][0] + bx, acc[mt][nt][1] + by);
            float2 t1 = make_float2(acc[mt][nt][2] + bx, acc[mt][nt][3] + by);
            *(float2*)(Y + (size_t)row0 * Dn + col0)       = t0;
            *(float2*)(Y + (size_t)(row0 + 8) * Dn + col0) = t1;
        }
    }
}

// ---------------------------------------------------------------------------
// Tensor-core flash attention (mma.sync bf16 hi/lo split everywhere).
// CTA = 128 queries x one (b,h); 8 warps x 16 queries; 64-key tiles.
// Q/K smem [row][72] bf16; V smem [key][72] bf16, B-frags via ldmatrix.trans.
// ---------------------------------------------------------------------------
#define QST 72
#define SZ_Q   (128 * QST * 2)        // 18432 per copy
#define SZ_KV  (64 * QST * 2)         // 9216 per copy
#define OFF_QHI 0
#define OFF_QLO (OFF_QHI + SZ_Q)
#define OFF_KHI (OFF_QLO + SZ_Q)
#define OFF_KLO (OFF_KHI + SZ_KV)
#define OFF_VHI (OFF_KLO + SZ_KV)
#define OFF_VLO (OFF_VHI + SZ_KV)
#define ATTN_SMEM (OFF_VLO + SZ_KV)   // 73728

__global__ void __launch_bounds__(256)
attn_mma_kernel(const float* __restrict__ Q, const float* __restrict__ K,
                const float* __restrict__ V, float* __restrict__ O)
{
    extern __shared__ char sm[];
    const uint32_t sb = smem_u32(sm);
    __nv_bfloat16* qhi = (__nv_bfloat16*)(sm + OFF_QHI);
    __nv_bfloat16* qlo = (__nv_bfloat16*)(sm + OFF_QLO);
    __nv_bfloat16* khi = (__nv_bfloat16*)(sm + OFF_KHI);
    __nv_bfloat16* klo = (__nv_bfloat16*)(sm + OFF_KLO);
    __nv_bfloat16* vhi = (__nv_bfloat16*)(sm + OFF_VHI);
    __nv_bfloat16* vlo = (__nv_bfloat16*)(sm + OFF_VLO);

    const int tid  = threadIdx.x;
    const int wid  = tid >> 5;
    const int lane = tid & 31;
    const int fr = lane >> 2;
    const int fc = (lane & 3) * 2;
    const int bh = blockIdx.y;
    const int b  = bh >> 4;
    const int h  = bh & 15;
    const int q0 = blockIdx.x * 128;
    const int wq = wid * 16;

    // Load Q tile (scaled by 1/8), split hi/lo
#pragma unroll
    for (int i = 0; i < 8; i++) {
        int idx = tid + i * 256;
        int row = idx >> 4;
        int c4  = (idx & 15) << 2;
        float4 t = *(const float4*)(Q + (size_t)(b * Sn + q0 + row) * Dn + h * HDn + c4);
        t.x *= 0.125f; t.y *= 0.125f; t.z *= 0.125f; t.w *= 0.125f;
        uint32_t h01, l01, h23, l23;
        split2f(t.x, t.y, h01, l01);
        split2f(t.z, t.w, h23, l23);
        *(uint32_t*)&qhi[row * QST + c4]     = h01;
        *(uint32_t*)&qhi[row * QST + c4 + 2] = h23;
        *(uint32_t*)&qlo[row * QST + c4]     = l01;
        *(uint32_t*)&qlo[row * QST + c4 + 2] = l23;
    }

    float o[8][4];
#pragma unroll
    for (int nt = 0; nt < 8; nt++)
#pragma unroll
        for (int e = 0; e < 4; e++) o[nt][e] = 0.f;
    float m0 = -1e30f, m1 = -1e30f, l0 = 0.f, l1 = 0.f;

    for (int k0 = 0; k0 < Sn; k0 += 64) {
        // Load K/V tiles, split hi/lo
#pragma unroll
        for (int i = 0; i < 4; i++) {
            int idx = tid + i * 256;
            int row = idx >> 4;
            int c4  = (idx & 15) << 2;
            const size_t go = (size_t)(b * Sn + k0 + row) * Dn + h * HDn + c4;
            float4 kt = *(const float4*)(K + go);
            float4 vt = *(const float4*)(V + go);
            uint32_t h01, l01, h23, l23;
            split2f(kt.x, kt.y, h01, l01);
            split2f(kt.z, kt.w, h23, l23);
            *(uint32_t*)&khi[row * QST + c4]     = h01;
            *(uint32_t*)&khi[row * QST + c4 + 2] = h23;
            *(uint32_t*)&klo[row * QST + c4]     = l01;
            *(uint32_t*)&klo[row * QST + c4 + 2] = l23;
            split2f(vt.x, vt.y, h01, l01);
            split2f(vt.z, vt.w, h23, l23);
            *(uint32_t*)&vhi[row * QST + c4]     = h01;
            *(uint32_t*)&vhi[row * QST + c4 + 2] = h23;
            *(uint32_t*)&vlo[row * QST + c4]     = l01;
            *(uint32_t*)&vlo[row * QST + c4 + 2] = l23;
        }
        __syncthreads();

        // S = (Qhi+Qlo) * (Khi+Klo)^T  (3-pass)
        float s[8][4];
#pragma unroll
        for (int nt = 0; nt < 8; nt++)
#pragma unroll
            for (int e = 0; e < 4; e++) s[nt][e] = 0.f;

#pragma unroll
        for (int kk = 0; kk < 64; kk += 16) {
            uint32_t ah[4], al[4];
            ah[0] = *(const uint32_t*)&qhi[(wq + fr) * QST + kk + fc];
            ah[1] = *(const uint32_t*)&qhi[(wq + fr + 8) * QST + kk + fc];
            ah[2] = *(const uint32_t*)&qhi[(wq + fr) * QST + kk + fc + 8];
            ah[3] = *(const uint32_t*)&qhi[(wq + fr + 8) * QST + kk + fc + 8];
            al[0] = *(const uint32_t*)&qlo[(wq + fr) * QST + kk + fc];
            al[1] = *(const uint32_t*)&qlo[(wq + fr + 8) * QST + kk + fc];
            al[2] = *(const uint32_t*)&qlo[(wq + fr) * QST + kk + fc + 8];
            al[3] = *(const uint32_t*)&qlo[(wq + fr + 8) * QST + kk + fc + 8];
#pragma unroll
            for (int nt = 0; nt < 8; nt++) {
                uint32_t bh2[2], bl2[2];
                bh2[0] = *(const uint32_t*)&khi[(nt * 8 + fr) * QST + kk + fc];
                bh2[1] = *(const uint32_t*)&khi[(nt * 8 + fr) * QST + kk + fc + 8];
                bl2[0] = *(const uint32_t*)&klo[(nt * 8 + fr) * QST + kk + fc];
                bl2[1] = *(const uint32_t*)&klo[(nt * 8 + fr) * QST + kk + fc + 8];
                mma16816(s[nt], ah, bh2);
                mma16816(s[nt], ah, bl2);
                mma16816(s[nt], al, bh2);
            }
        }

        // Online softmax: thread owns rows fr (elems 0,1) and fr+8 (elems 2,3)
        float r0 = -1e30f, r1 = -1e30f;
#pragma unroll
        for (int nt = 0; nt < 8; nt++) {
            r0 = fmaxf(r0, fmaxf(s[nt][0], s[nt][1]));
            r1 = fmaxf(r1, fmaxf(s[nt][2], s[nt][3]));
        }
        r0 = fmaxf(r0, __shfl_xor_sync(0xffffffffu, r0, 1));
        r0 = fmaxf(r0, __shfl_xor_sync(0xffffffffu, r0, 2));
        r1 = fmaxf(r1, __shfl_xor_sync(0xffffffffu, r1, 1));
        r1 = fmaxf(r1, __shfl_xor_sync(0xffffffffu, r1, 2));
        const float mn0 = fmaxf(m0, r0);
        const float mn1 = fmaxf(m1, r1);
        const float c0 = __expf(m0 - mn0);
        const float c1 = __expf(m1 - mn1);
        m0 = mn0; m1 = mn1;

        float ps0 = 0.f, ps1 = 0.f;
#pragma unroll
        for (int nt = 0; nt < 8; nt++) {
            s[nt][0] = __expf(s[nt][0] - mn0);
            s[nt][1] = __expf(s[nt][1] - mn0);
            s[nt][2] = __expf(s[nt][2] - mn1);
            s[nt][3] = __expf(s[nt][3] - mn1);
            ps0 += s[nt][0] + s[nt][1];
            ps1 += s[nt][2] + s[nt][3];
        }
        ps0 += __shfl_xor_sync(0xffffffffu, ps0, 1);
        ps0 += __shfl_xor_sync(0xffffffffu, ps0, 2);
        ps1 += __shfl_xor_sync(0xffffffffu, ps1, 1);
        ps1 += __shfl_xor_sync(0xffffffffu, ps1, 2);
        l0 = l0 * c0 + ps0;
        l1 = l1 * c1 + ps1;
#pragma unroll
        for (int nt = 0; nt < 8; nt++) {
            o[nt][0] *= c0; o[nt][1] *= c0;
            o[nt][2] *= c1; o[nt][3] *= c1;
        }

        // P fragments: C-layout -> A-layout identity, with hi/lo split
        uint32_t ph[4][4], pl[4][4];
#pragma unroll
        for (int kk2 = 0; kk2 < 4; kk2++) {
            const int nt0 = 2 * kk2, nt1 = 2 * kk2 + 1;
            split2f(s[nt0][0], s[nt0][1], ph[kk2][0], pl[kk2][0]);
            split2f(s[nt0][2], s[nt0][3], ph[kk2][1], pl[kk2][1]);
            split2f(s[nt1][0], s[nt1][1], ph[kk2][2], pl[kk2][2]);
            split2f(s[nt1][2], s[nt1][3], ph[kk2][3], pl[kk2][3]);
        }

        // O += (Phi+Plo) * (Vhi+Vlo)   (3-pass), B-frags via ldmatrix.trans
        const uint32_t lrow = lane & 15;
        const uint32_t lcol8 = (lane >> 4) * 8;
#pragma unroll
        for (int kk2 = 0; kk2 < 4; kk2++) {
            const uint32_t roff = (uint32_t)((kk2 * 16 + lrow) * QST) * 2;
#pragma unroll
            for (int np = 0; np < 4; np++) {
                const uint32_t coff = (uint32_t)(np * 16 + lcol8) * 2;
                uint32_t bh0, bh1, bh2, bh3, bl0, bl1, bl2, bl3;
                LDSM_X4_T(bh0, bh1, bh2, bh3, sb + OFF_VHI + roff + coff);
                LDSM_X4_T(bl0, bl1, bl2, bl3, sb + OFF_VLO + roff + coff);
                uint32_t bhA[2] = {bh0, bh1}, bhB[2] = {bh2, bh3};
                uint32_t blA[2] = {bl0, bl1}, blB[2] = {bl2, bl3};
                mma16816(o[2 * np],     ph[kk2], bhA);
                mma16816(o[2 * np],     ph[kk2], blA);
                mma16816(o[2 * np],     pl[kk2], bhA);
                mma16816(o[2 * np + 1], ph[kk2], bhB);
                mma16816(o[2 * np + 1], ph[kk2], blB);
                mma16816(o[2 * np + 1], pl[kk2], bhB);
            }
        }
        __syncthreads();
    }

    // Epilogue
    const float inv0 = 1.f / l0;
    const float inv1 = 1.f / l1;
    const int row0 = q0 + wq + fr;
#pragma unroll
    for (int nt = 0; nt < 8; nt++) {
        const int col = h * HDn + nt * 8 + fc;
        *(float2*)(O + (size_t)(b * Sn + row0) * Dn + col) =
            make_float2(o[nt][0] * inv0, o[nt][1] * inv0);
        *(float2*)(O + (size_t)(b * Sn + row0 + 8) * Dn + col) =
            make_float2(o[nt][2] * inv1, o[nt][3] * inv1);
    }
}

// ---------------------------------------------------------------------------
extern "C" void kernel_launch(void* const* d_in, const int* in_sizes, int n_in,
                              void* d_out, int out_size)
{
    (void)in_sizes; (void)n_in; (void)out_size;

    const float* q    = (const float*)d_in[0];
    const float* k    = (const float*)d_in[1];
    const float* v    = (const float*)d_in[2];
    const float* w_q  = (const float*)d_in[3];
    const float* b_q  = (const float*)d_in[4];
    const float* w_k  = (const float*)d_in[5];
    const float* b_k  = (const float*)d_in[6];
    const float* w_v  = (const float*)d_in[7];
    const float* b_v  = (const float*)d_in[8];
    const float* w_fc = (const float*)d_in[9];
    const float* b_fc = (const float*)d_in[10];
    float* out = (float*)d_out;

    cudaStreamCaptureStatus cs = cudaStreamCaptureStatusNone;
    cudaStreamIsCapturing(cudaStreamLegacy, &cs);
    if (cs == cudaStreamCaptureStatusNone) {
        cudaFuncSetAttribute(attn_mma_kernel,
                             cudaFuncAttributeMaxDynamicSharedMemorySize, ATTN_SMEM);
    }

    float *gQ, *gK, *gV, *gX;
    cudaGetSymbolAddress((void**)&gQ, g_Q);
    cudaGetSymbolAddress((void**)&gK, g_K);
    cudaGetSymbolAddress((void**)&gV, g_V);
    cudaGetSymbolAddress((void**)&gX, g_X);

    dim3 ggrid(Dn / BN, MTOK / BM);     // (8, 64)
    gemm_mma_kernel<<<ggrid, 256>>>(q, w_q, b_q, gQ);
    gemm_mma_kernel<<<ggrid, 256>>>(k, w_k, b_k, gK);
    gemm_mma_kernel<<<ggrid, 256>>>(v, w_v, b_v, gV);

    dim3 agrid(Sn / 128, Bn * Hn);      // (16, 64)
    attn_mma_kernel<<<agrid, 256, ATTN_SMEM>>>(gQ, gK, gV, gX);

    gemm_mma_kernel<<<ggrid, 256>>>(gX, w_fc, b_fc, out);
}

// round 5
// speedup vs baseline: 9.0197x; 1.1538x over previous
#include <cuda_runtime.h>
#include <cuda_bf16.h>
#include <cuda_fp16.h>
#include <cstdint>
#include <math.h>

#define Bn  4
#define Sn  2048
#define Dn  1024
#define Hn  16
#define HDn 64
#define MTOK 8192

// ---------------------------------------------------------------------------
// Scratch (allocation-free rule: __device__ globals)
// ---------------------------------------------------------------------------
__device__ __nv_bfloat16 g_qh[MTOK * Dn], g_ql[MTOK * Dn];
__device__ __nv_bfloat16 g_kh[MTOK * Dn], g_kl[MTOK * Dn];
__device__ __nv_bfloat16 g_vh[MTOK * Dn], g_vl[MTOK * Dn];
__device__ __nv_bfloat16 g_wqh[Dn * Dn], g_wql[Dn * Dn];
__device__ __nv_bfloat16 g_wkh[Dn * Dn], g_wkl[Dn * Dn];
__device__ __nv_bfloat16 g_wvh[Dn * Dn], g_wvl[Dn * Dn];
__device__ __nv_bfloat16 g_wfh[Dn * Dn], g_wfl[Dn * Dn];
__device__ __nv_bfloat16 g_Qh[MTOK * Dn], g_Ql[MTOK * Dn];
__device__ __nv_bfloat16 g_Kh[MTOK * Dn], g_Kl[MTOK * Dn];
__device__ __half        g_Vf[MTOK * Dn];
__device__ __nv_bfloat16 g_Xh[MTOK * Dn], g_Xl[MTOK * Dn];

// ---------------------------------------------------------------------------
// Helpers
// ---------------------------------------------------------------------------
__device__ __forceinline__ uint32_t smem_u32(const void* p) {
    uint32_t a;
    asm("{ .reg .u64 t; cvta.to.shared.u64 t, %1; cvt.u32.u64 %0, t; }" : "=r"(a) : "l"(p));
    return a;
}

// Pack (x -> low, y -> high) bf16x2 + residual pair.
__device__ __forceinline__ void split2f(float x, float y, uint32_t& hi, uint32_t& lo) {
    uint32_t h;
    asm("cvt.rn.bf16x2.f32 %0, %1, %2;" : "=r"(h) : "f"(y), "f"(x));
    float hx = __uint_as_float(h << 16);
    float hy = __uint_as_float(h & 0xffff0000u);
    asm("cvt.rn.bf16x2.f32 %0, %1, %2;" : "=r"(lo) : "f"(y - hy), "f"(x - hx));
    hi = h;
}

__device__ __forceinline__ uint32_t pack_f16x2(float x, float y) {
    uint32_t r;
    asm("cvt.rn.f16x2.f32 %0, %1, %2;" : "=r"(r) : "f"(y), "f"(x));
    return r;
}

__device__ __forceinline__ void mma16816(float* d, const uint32_t* a, const uint32_t* b) {
    asm volatile(
        "mma.sync.aligned.m16n8k16.row.col.f32.bf16.bf16.f32 "
        "{%0,%1,%2,%3}, {%4,%5,%6,%7}, {%8,%9}, {%0,%1,%2,%3};"
        : "+f"(d[0]), "+f"(d[1]), "+f"(d[2]), "+f"(d[3])
        : "r"(a[0]), "r"(a[1]), "r"(a[2]), "r"(a[3]), "r"(b[0]), "r"(b[1]));
}

__device__ __forceinline__ void mma16816h(float* d, const uint32_t* a, const uint32_t* b) {
    asm volatile(
        "mma.sync.aligned.m16n8k16.row.col.f32.f16.f16.f32 "
        "{%0,%1,%2,%3}, {%4,%5,%6,%7}, {%8,%9}, {%0,%1,%2,%3};"
        : "+f"(d[0]), "+f"(d[1]), "+f"(d[2]), "+f"(d[3])
        : "r"(a[0]), "r"(a[1]), "r"(a[2]), "r"(a[3]), "r"(b[0]), "r"(b[1]));
}

#define LDSM_X4_T(r0, r1, r2, r3, addr) \
    asm volatile("ldmatrix.sync.aligned.m8n8.x4.trans.shared.b16 {%0,%1,%2,%3}, [%4];" \
                 : "=r"(r0), "=r"(r1), "=r"(r2), "=r"(r3) : "r"(addr))

#define CP_A16(dst, src) \
    asm volatile("cp.async.cg.shared.global [%0], [%1], 16;" :: "r"(dst), "l"(src))
#define CP_COMMIT() asm volatile("cp.async.commit_group;")

// ---------------------------------------------------------------------------
// Split: fp32 -> bf16 hi + bf16 lo (elementwise)
// ---------------------------------------------------------------------------
__global__ void __launch_bounds__(256)
split_kernel(const float* __restrict__ src, __nv_bfloat16* __restrict__ hi,
             __nv_bfloat16* __restrict__ lo, int n)
{
    int i = (blockIdx.x * 256 + threadIdx.x) * 4;
    if (i >= n) return;
    float4 v = *(const float4*)(src + i);
    uint32_t h01, l01, h23, l23;
    split2f(v.x, v.y, h01, l01);
    split2f(v.z, v.w, h23, l23);
    *(uint2*)(hi + i) = make_uint2(h01, h23);
    *(uint2*)(lo + i) = make_uint2(l01, l23);
}

// ---------------------------------------------------------------------------
// GEMM: Y = X[M,K]*W[N,K]^T + bias, bf16 hi/lo operands from gmem,
// cp.async 2-stage double buffer. CTA 128x128, BK=32, 8 warps (2x4), 64x32.
// mode: 0 -> fp32 Yf; 1 -> split bf16 (Yhi,Ylo); 2 -> fp16 Yh.
// ---------------------------------------------------------------------------
#define GST 40
#define G_ARR_B   (128 * GST * 2)     // 10240
#define G_STAGE_B (4 * G_ARR_B)       // 40960
#define GEMM_SMEM (2 * G_STAGE_B)     // 81920

__global__ void __launch_bounds__(256, 2)
gemm_bf16(const __nv_bfloat16* __restrict__ Ahi, const __nv_bfloat16* __restrict__ Alo,
          const __nv_bfloat16* __restrict__ Bhi, const __nv_bfloat16* __restrict__ Blo,
          const float* __restrict__ bias, float scale, int mode,
          float* __restrict__ Yf, __nv_bfloat16* __restrict__ Yhi,
          __nv_bfloat16* __restrict__ Ylo, __half* __restrict__ Yh)
{
    extern __shared__ char sm[];
    const uint32_t sb = smem_u32(sm);
    const int tid = threadIdx.x, wid = tid >> 5, lane = tid & 31;
    const int bm = blockIdx.y * 128, bn = blockIdx.x * 128;
    const int wm = (wid & 1) * 64, wn = (wid >> 1) * 32;
    const int fr = lane >> 2, fc = (lane & 3) * 2;

    float acc[4][4][4];
#pragma unroll
    for (int mt = 0; mt < 4; mt++)
#pragma unroll
        for (int nt = 0; nt < 4; nt++)
#pragma unroll
            for (int e = 0; e < 4; e++) acc[mt][nt][e] = 0.f;

    // Stage loader: arr = i>>1 (compile-time per unrolled i): 0=Ahi 1=Alo 2=Bhi 3=Blo
    auto load_stage = [&](int stage, int k0) {
#pragma unroll
        for (int i = 0; i < 8; i++) {
            const int arr = i >> 1;
            int rem = tid + (i & 1) * 256;   // 0..511
            int row = rem >> 2;
            int ch  = rem & 3;
            size_t goff = (size_t)((arr < 2 ? bm : bn) + row) * Dn + k0 + ch * 8;
            const __nv_bfloat16* src =
                (arr == 0) ? Ahi + goff : (arr == 1) ? Alo + goff
                : (arr == 2) ? Bhi + goff : Blo + goff;
            uint32_t dst = sb + stage * G_STAGE_B + arr * G_ARR_B + row * (GST * 2) + ch * 16;
            CP_A16(dst, src);
        }
        CP_COMMIT();
    };

    load_stage(0, 0);

    for (int t = 0; t < 32; t++) {
        if (t < 31) {
            load_stage((t + 1) & 1, (t + 1) * 32);
            asm volatile("cp.async.wait_group 1;");
        } else {
            asm volatile("cp.async.wait_group 0;");
        }
        __syncthreads();

        const __nv_bfloat16* sAh = (const __nv_bfloat16*)(sm + (t & 1) * G_STAGE_B);
        const __nv_bfloat16* sAl = sAh + G_ARR_B / 2;
        const __nv_bfloat16* sBh = sAh + G_ARR_B;
        const __nv_bfloat16* sBl = sAh + 3 * (G_ARR_B / 2);

#pragma unroll
        for (int ks = 0; ks < 2; ks++) {
            const int kk = ks * 16;
            uint32_t ahi[4][4], alo[4][4];
#pragma unroll
            for (int mt = 0; mt < 4; mt++) {
                const int m0 = wm + mt * 16;
                ahi[mt][0] = *(const uint32_t*)&sAh[(m0 + fr) * GST + kk + fc];
                ahi[mt][1] = *(const uint32_t*)&sAh[(m0 + fr + 8) * GST + kk + fc];
                ahi[mt][2] = *(const uint32_t*)&sAh[(m0 + fr) * GST + kk + fc + 8];
                ahi[mt][3] = *(const uint32_t*)&sAh[(m0 + fr + 8) * GST + kk + fc + 8];
                alo[mt][0] = *(const uint32_t*)&sAl[(m0 + fr) * GST + kk + fc];
                alo[mt][1] = *(const uint32_t*)&sAl[(m0 + fr + 8) * GST + kk + fc];
                alo[mt][2] = *(const uint32_t*)&sAl[(m0 + fr) * GST + kk + fc + 8];
                alo[mt][3] = *(const uint32_t*)&sAl[(m0 + fr + 8) * GST + kk + fc + 8];
            }
#pragma unroll
            for (int nt = 0; nt < 4; nt++) {
                const int n0 = wn + nt * 8;
                uint32_t bh2[2], bl2[2];
                bh2[0] = *(const uint32_t*)&sBh[(n0 + fr) * GST + kk + fc];
                bh2[1] = *(const uint32_t*)&sBh[(n0 + fr) * GST + kk + fc + 8];
                bl2[0] = *(const uint32_t*)&sBl[(n0 + fr) * GST + kk + fc];
                bl2[1] = *(const uint32_t*)&sBl[(n0 + fr) * GST + kk + fc + 8];
#pragma unroll
                for (int mt = 0; mt < 4; mt++) {
                    mma16816(acc[mt][nt], ahi[mt], bh2);
                    mma16816(acc[mt][nt], ahi[mt], bl2);
                    mma16816(acc[mt][nt], alo[mt], bh2);
                }
            }
        }
        __syncthreads();
    }

    // Epilogue
#pragma unroll
    for (int mt = 0; mt < 4; mt++) {
        const int row0 = bm + wm + mt * 16 + fr;
#pragma unroll
        for (int nt = 0; nt < 4; nt++) {
            const int col0 = bn + wn + nt * 8 + fc;
            const float bx = bias[col0], by = bias[col0 + 1];
            float v00 = (acc[mt][nt][0] + bx) * scale;
            float v01 = (acc[mt][nt][1] + by) * scale;
            float v10 = (acc[mt][nt][2] + bx) * scale;
            float v11 = (acc[mt][nt][3] + by) * scale;
            const size_t o0 = (size_t)row0 * Dn + col0;
            const size_t o1 = (size_t)(row0 + 8) * Dn + col0;
            if (mode == 0) {
                *(float2*)(Yf + o0) = make_float2(v00, v01);
                *(float2*)(Yf + o1) = make_float2(v10, v11);
            } else if (mode == 1) {
                uint32_t hv, lv;
                split2f(v00, v01, hv, lv);
                *(uint32_t*)(Yhi + o0) = hv;
                *(uint32_t*)(Ylo + o0) = lv;
                split2f(v10, v11, hv, lv);
                *(uint32_t*)(Yhi + o1) = hv;
                *(uint32_t*)(Ylo + o1) = lv;
            } else {
                *(uint32_t*)(Yh + o0) = pack_f16x2(v00, v01);
                *(uint32_t*)(Yh + o1) = pack_f16x2(v10, v11);
            }
        }
    }
}

// ---------------------------------------------------------------------------
// Flash attention. Q pre-split/pre-scaled bf16 (frags in regs), K hi/lo bf16
// + V fp16 tiles double-buffered via cp.async. QK^T bf16 3-pass; PV fp16
// single-pass. CTA = 128 queries x (b,h); 8 warps x 16 q; 64-key tiles.
// ---------------------------------------------------------------------------
#define AST 72
#define A_ARR_B   (64 * AST * 2)      // 9216
#define A_STAGE_B (3 * A_ARR_B)       // 27648
#define ATTN_SMEM (2 * A_STAGE_B)     // 55296

__global__ void __launch_bounds__(256, 2)
attn_mma2_kernel(const __nv_bfloat16* __restrict__ Qh, const __nv_bfloat16* __restrict__ Ql,
                 const __nv_bfloat16* __restrict__ Kh, const __nv_bfloat16* __restrict__ Kl,
                 const __half* __restrict__ Vf,
                 __nv_bfloat16* __restrict__ Xh, __nv_bfloat16* __restrict__ Xl)
{
    extern __shared__ char sm[];
    const uint32_t sb = smem_u32(sm);
    const int tid = threadIdx.x, wid = tid >> 5, lane = tid & 31;
    const int fr = lane >> 2, fc = (lane & 3) * 2;
    const int bh = blockIdx.y;
    const int b = bh >> 4, h = bh & 15;
    const int q0 = blockIdx.x * 128;
    const int wq = wid * 16;

    // Q fragments in registers (Q is already scaled by 1/8)
    uint32_t qa_h[4][4], qa_l[4][4];
    {
        const size_t r0 = (size_t)(b * Sn + q0 + wq + fr) * Dn + h * HDn;
        const size_t r8 = (size_t)(b * Sn + q0 + wq + fr + 8) * Dn + h * HDn;
#pragma unroll
        for (int k4 = 0; k4 < 4; k4++) {
            const int kk = k4 * 16;
            qa_h[k4][0] = *(const uint32_t*)(Qh + r0 + kk + fc);
            qa_h[k4][1] = *(const uint32_t*)(Qh + r8 + kk + fc);
            qa_h[k4][2] = *(const uint32_t*)(Qh + r0 + kk + fc + 8);
            qa_h[k4][3] = *(const uint32_t*)(Qh + r8 + kk + fc + 8);
            qa_l[k4][0] = *(const uint32_t*)(Ql + r0 + kk + fc);
            qa_l[k4][1] = *(const uint32_t*)(Ql + r8 + kk + fc);
            qa_l[k4][2] = *(const uint32_t*)(Ql + r0 + kk + fc + 8);
            qa_l[k4][3] = *(const uint32_t*)(Ql + r8 + kk + fc + 8);
        }
    }

    // KV stage loader: i>>1: 0=Kh 1=Kl 2=Vf
    auto load_kv = [&](int stage, int k0) {
#pragma unroll
        for (int i = 0; i < 6; i++) {
            const int arr = i >> 1;
            int rem = tid + (i & 1) * 256;   // 0..511
            int row = rem >> 3;
            int ch  = rem & 7;
            size_t go = (size_t)(b * Sn + k0 + row) * Dn + h * HDn + ch * 8;
            const void* src = (arr == 0) ? (const void*)(Kh + go)
                             : (arr == 1) ? (const void*)(Kl + go)
                             : (const void*)(Vf + go);
            uint32_t dst = sb + stage * A_STAGE_B + arr * A_ARR_B + row * (AST * 2) + ch * 16;
            CP_A16(dst, src);
        }
        CP_COMMIT();
    };

    float o[8][4];
#pragma unroll
    for (int nt = 0; nt < 8; nt++)
#pragma unroll
        for (int e = 0; e < 4; e++) o[nt][e] = 0.f;
    float m0 = -1e30f, m1 = -1e30f, l0 = 0.f, l1 = 0.f;

    load_kv(0, 0);

    for (int t = 0; t < 32; t++) {
        if (t < 31) {
            load_kv((t + 1) & 1, (t + 1) * 64);
            asm volatile("cp.async.wait_group 1;");
        } else {
            asm volatile("cp.async.wait_group 0;");
        }
        __syncthreads();

        const __nv_bfloat16* skh = (const __nv_bfloat16*)(sm + (t & 1) * A_STAGE_B);
        const __nv_bfloat16* skl = skh + A_ARR_B / 2;
        const uint32_t vbase = sb + (t & 1) * A_STAGE_B + 2 * A_ARR_B;

        // S = Q * K^T (bf16 3-pass)
        float s[8][4];
#pragma unroll
        for (int nt = 0; nt < 8; nt++)
#pragma unroll
            for (int e = 0; e < 4; e++) s[nt][e] = 0.f;

#pragma unroll
        for (int k4 = 0; k4 < 4; k4++) {
            const int kk = k4 * 16;
#pragma unroll
            for (int nt = 0; nt < 8; nt++) {
                uint32_t bh2[2], bl2[2];
                bh2[0] = *(const uint32_t*)&skh[(nt * 8 + fr) * AST + kk + fc];
                bh2[1] = *(const uint32_t*)&skh[(nt * 8 + fr) * AST + kk + fc + 8];
                bl2[0] = *(const uint32_t*)&skl[(nt * 8 + fr) * AST + kk + fc];
                bl2[1] = *(const uint32_t*)&skl[(nt * 8 + fr) * AST + kk + fc + 8];
                mma16816(s[nt], qa_h[k4], bh2);
                mma16816(s[nt], qa_h[k4], bl2);
                mma16816(s[nt], qa_l[k4], bh2);
            }
        }

        // Online softmax (rows fr / fr+8)
        float r0 = -1e30f, r1 = -1e30f;
#pragma unroll
        for (int nt = 0; nt < 8; nt++) {
            r0 = fmaxf(r0, fmaxf(s[nt][0], s[nt][1]));
            r1 = fmaxf(r1, fmaxf(s[nt][2], s[nt][3]));
        }
        r0 = fmaxf(r0, __shfl_xor_sync(0xffffffffu, r0, 1));
        r0 = fmaxf(r0, __shfl_xor_sync(0xffffffffu, r0, 2));
        r1 = fmaxf(r1, __shfl_xor_sync(0xffffffffu, r1, 1));
        r1 = fmaxf(r1, __shfl_xor_sync(0xffffffffu, r1, 2));
        const float mn0 = fmaxf(m0, r0);
        const float mn1 = fmaxf(m1, r1);
        const float c0 = __expf(m0 - mn0);
        const float c1 = __expf(m1 - mn1);
        m0 = mn0; m1 = mn1;

        float ps0 = 0.f, ps1 = 0.f;
#pragma unroll
        for (int nt = 0; nt < 8; nt++) {
            s[nt][0] = __expf(s[nt][0] - mn0);
            s[nt][1] = __expf(s[nt][1] - mn0);
            s[nt][2] = __expf(s[nt][2] - mn1);
            s[nt][3] = __expf(s[nt][3] - mn1);
            ps0 += s[nt][0] + s[nt][1];
            ps1 += s[nt][2] + s[nt][3];
        }
        ps0 += __shfl_xor_sync(0xffffffffu, ps0, 1);
        ps0 += __shfl_xor_sync(0xffffffffu, ps0, 2);
        ps1 += __shfl_xor_sync(0xffffffffu, ps1, 1);
        ps1 += __shfl_xor_sync(0xffffffffu, ps1, 2);
        l0 = l0 * c0 + ps0;
        l1 = l1 * c1 + ps1;
#pragma unroll
        for (int nt = 0; nt < 8; nt++) {
            o[nt][0] *= c0; o[nt][1] *= c0;
            o[nt][2] *= c1; o[nt][3] *= c1;
        }

        // P fragments (fp16, single precision pass): C-layout == A-layout
        uint32_t pf[4][4];
#pragma unroll
        for (int k2 = 0; k2 < 4; k2++) {
            const int n0 = 2 * k2, n1 = 2 * k2 + 1;
            pf[k2][0] = pack_f16x2(s[n0][0], s[n0][1]);
            pf[k2][1] = pack_f16x2(s[n0][2], s[n0][3]);
            pf[k2][2] = pack_f16x2(s[n1][0], s[n1][1]);
            pf[k2][3] = pack_f16x2(s[n1][2], s[n1][3]);
        }

        // O += P * V (fp16 single pass), B-frags via ldmatrix.trans
        const uint32_t lrow = lane & 15;
        const uint32_t lcol8 = (lane >> 4) * 8;
#pragma unroll
        for (int k2 = 0; k2 < 4; k2++) {
            const uint32_t roff = (uint32_t)((k2 * 16 + lrow) * AST) * 2;
#pragma unroll
            for (int np = 0; np < 4; np++) {
                const uint32_t coff = (uint32_t)(np * 16 + lcol8) * 2;
                uint32_t v0, v1, v2, v3;
                LDSM_X4_T(v0, v1, v2, v3, vbase + roff + coff);
                uint32_t bA[2] = {v0, v1}, bB[2] = {v2, v3};
                mma16816h(o[2 * np],     pf[k2], bA);
                mma16816h(o[2 * np + 1], pf[k2], bB);
            }
        }
        __syncthreads();
    }

    // Epilogue: write X split bf16
    const float inv0 = 1.f / l0;
    const float inv1 = 1.f / l1;
    const int row0 = q0 + wq + fr;
#pragma unroll
    for (int nt = 0; nt < 8; nt++) {
        const int col = h * HDn + nt * 8 + fc;
        const size_t o0 = (size_t)(b * Sn + row0) * Dn + col;
        const size_t o1 = (size_t)(b * Sn + row0 + 8) * Dn + col;
        uint32_t hv, lv;
        split2f(o[nt][0] * inv0, o[nt][1] * inv0, hv, lv);
        *(uint32_t*)(Xh + o0) = hv;
        *(uint32_t*)(Xl + o0) = lv;
        split2f(o[nt][2] * inv1, o[nt][3] * inv1, hv, lv);
        *(uint32_t*)(Xh + o1) = hv;
        *(uint32_t*)(Xl + o1) = lv;
    }
}

// ---------------------------------------------------------------------------
extern "C" void kernel_launch(void* const* d_in, const int* in_sizes, int n_in,
                              void* d_out, int out_size)
{
    (void)in_sizes; (void)n_in; (void)out_size;

    const float* q    = (const float*)d_in[0];
    const float* k    = (const float*)d_in[1];
    const float* v    = (const float*)d_in[2];
    const float* w_q  = (const float*)d_in[3];
    const float* b_q  = (const float*)d_in[4];
    const float* w_k  = (const float*)d_in[5];
    const float* b_k  = (const float*)d_in[6];
    const float* w_v  = (const float*)d_in[7];
    const float* b_v  = (const float*)d_in[8];
    const float* w_fc = (const float*)d_in[9];
    const float* b_fc = (const float*)d_in[10];
    float* out = (float*)d_out;

    cudaStreamCaptureStatus cs = cudaStreamCaptureStatusNone;
    cudaStreamIsCapturing(cudaStreamLegacy, &cs);
    if (cs == cudaStreamCaptureStatusNone) {
        cudaFuncSetAttribute(gemm_bf16,
                             cudaFuncAttributeMaxDynamicSharedMemorySize, GEMM_SMEM);
        cudaFuncSetAttribute(attn_mma2_kernel,
                             cudaFuncAttributeMaxDynamicSharedMemorySize, ATTN_SMEM);
    }

    __nv_bfloat16 *qh, *ql, *kh, *kl, *vh, *vl;
    __nv_bfloat16 *wqh, *wql, *wkh, *wkl, *wvh, *wvl, *wfh, *wfl;
    __nv_bfloat16 *Qh, *Ql, *Kh, *Kl, *Xh, *Xl;
    __half *Vf;
    cudaGetSymbolAddress((void**)&qh, g_qh);   cudaGetSymbolAddress((void**)&ql, g_ql);
    cudaGetSymbolAddress((void**)&kh, g_kh);   cudaGetSymbolAddress((void**)&kl, g_kl);
    cudaGetSymbolAddress((void**)&vh, g_vh);   cudaGetSymbolAddress((void**)&vl, g_vl);
    cudaGetSymbolAddress((void**)&wqh, g_wqh); cudaGetSymbolAddress((void**)&wql, g_wql);
    cudaGetSymbolAddress((void**)&wkh, g_wkh); cudaGetSymbolAddress((void**)&wkl, g_wkl);
    cudaGetSymbolAddress((void**)&wvh, g_wvh); cudaGetSymbolAddress((void**)&wvl, g_wvl);
    cudaGetSymbolAddress((void**)&wfh, g_wfh); cudaGetSymbolAddress((void**)&wfl, g_wfl);
    cudaGetSymbolAddress((void**)&Qh, g_Qh);   cudaGetSymbolAddress((void**)&Ql, g_Ql);
    cudaGetSymbolAddress((void**)&Kh, g_Kh);   cudaGetSymbolAddress((void**)&Kl, g_Kl);
    cudaGetSymbolAddress((void**)&Vf, g_Vf);
    cudaGetSymbolAddress((void**)&Xh, g_Xh);   cudaGetSymbolAddress((void**)&Xl, g_Xl);

    const int nIn = MTOK * Dn;          // 8M
    const int nW  = Dn * Dn;            // 1M
    split_kernel<<<nIn / 1024, 256>>>(q, qh, ql, nIn);
    split_kernel<<<nIn / 1024, 256>>>(k, kh, kl, nIn);
    split_kernel<<<nIn / 1024, 256>>>(v, vh, vl, nIn);
    split_kernel<<<nW / 1024, 256>>>(w_q, wqh, wql, nW);
    split_kernel<<<nW / 1024, 256>>>(w_k, wkh, wkl, nW);
    split_kernel<<<nW / 1024, 256>>>(w_v, wvh, wvl, nW);
    split_kernel<<<nW / 1024, 256>>>(w_fc, wfh, wfl, nW);

    dim3 ggrid(Dn / 128, MTOK / 128);   // (8, 64)
    // Q projection: pre-scale by 1/sqrt(HD)=0.125, split bf16 output
    gemm_bf16<<<ggrid, 256, GEMM_SMEM>>>(qh, ql, wqh, wql, b_q, 0.125f, 1,
                                         nullptr, Qh, Ql, nullptr);
    gemm_bf16<<<ggrid, 256, GEMM_SMEM>>>(kh, kl, wkh, wkl, b_k, 1.0f, 1,
                                         nullptr, Kh, Kl, nullptr);
    gemm_bf16<<<ggrid, 256, GEMM_SMEM>>>(vh, vl, wvh, wvl, b_v, 1.0f, 2,
                                         nullptr, nullptr, nullptr, Vf);

    dim3 agrid(Sn / 128, Bn * Hn);      // (16, 64)
    attn_mma2_kernel<<<agrid, 256, ATTN_SMEM>>>(Qh, Ql, Kh, Kl, Vf, Xh, Xl);

    gemm_bf16<<<ggrid, 256, GEMM_SMEM>>>(Xh, Xl, wfh, wfl, b_fc, 1.0f, 0,
                                         out, nullptr, nullptr, nullptr);
}